// round 11
// baseline (speedup 1.0000x reference)
#include <cuda_runtime.h>
#include <cuda_bf16.h>
#include <cstdint>

// NoiseFilter, exact closed form (validated R3-R7, rel_err ~3e-7):
//   taps: ir0[j] = (1/128)(amp0 + 2*sum_{k=1..63} amp_k cos(pi*k*j/64) + amp64*(-1)^j)
//         h[j]   = ir0[j] * 0.5*(1+cos(pi*j/64)),  j = 0..63
//   s[t] = 2*u[t]-1,  Z[192..255]=0, Z[256+t]=s[t]   (only [192,256) zeros are read)
//   out[tau] = sum_{d=0}^{63} h[d] * ( Z[256+tau-d] + Z[tau+d] )
// Wrap-tail (2nd term) only for output groups t0>=192 (q>=48): warps 6-7.
// Phase B: symmetric pairs — ir0(64-j)=E(j)-O(j), 33 workers/pair, coeffs read
// as LDS.128 quads. Taps stored duplicated (h,h) as uint64; conv loads them
// with ld.shared.v2.u64 (one LDS.128 broadcast -> two aligned FMA2 operands).

#define PAIRS   4
#define THREADS 256
#define ZSTRIDE 520            // 512 + 8 pad (16B row alignment)
#define PI64    0.04908738521234052f   // pi/64

#define PACK2(dst, lo, hi) \
    asm("mov.b64 %0, {%1, %2};" : "=l"(dst) \
        : "r"(__float_as_uint(lo)), "r"(__float_as_uint(hi)))
#define FMA2(acc, a, b) \
    asm("fma.rn.f32x2 %0, %1, %2, %0;" : "+l"(acc) : "l"(a), "l"(b))
#define ADD2(dst, a, b) \
    asm("add.rn.f32x2 %0, %1, %2;" : "=l"(dst) : "l"(a), "l"(b))
#define UNPACK2(lo, hi, v) \
    asm("mov.b64 {%0, %1}, %2;" : "=r"(lo), "=r"(hi) : "l"(v))
// one LDS.128 broadcast -> two taps, each landing in an aligned register pair;
// address computed into the register operand (ptxas folds hbase+const -> [imm])
#define LDSH2(h0, h1, addr) \
    asm volatile("ld.shared.v2.u64 {%0, %1}, [%2];" \
                 : "=l"(h0), "=l"(h1) : "r"(addr))

__global__ __launch_bounds__(THREADS)
void noisefilter_kernel(const float* __restrict__ amp,    // [65536, 65]
                        const float* __restrict__ noise,  // [65536, 256]
                        float*       __restrict__ out)    // [65536, 256]
{
    __shared__ __align__(16) float    Z[PAIRS][ZSTRIDE];  // padded signal
    __shared__ __align__(16) uint64_t hd64[PAIRS][64];    // duplicated taps (h,h)
    __shared__ __align__(16) float    a_sh[PAIRS][68];    // 2*amp

    const int tid = threadIdx.x;

    // tid -> (p, q): q<48 (tail-free) fills warps 0..5; q>=48 warps 6..7.
    int p, q;
    if (tid < 192) { p = tid / 48;      q = tid % 48; }
    else           { int r = tid - 192; p = r >> 4;   q = 48 + (r & 15); }

    const long long pairBase = (long long)blockIdx.x * PAIRS;

    // ---- issue global noise load early ----
    const float4* n4 = (const float4*)noise;
    float4 v = n4[(pairBase + p) * 64 + q];

    // ---- phase A: zero only Z[192..256) per pair; load amp (doubled) ----
    if (tid < 64) {
        int pp  = tid >> 4;
        int idx = 48 + (tid & 15);           // float4 idx 48..63 = floats 192..255
        ((float4*)(Z[pp]))[idx] = make_float4(0.f, 0.f, 0.f, 0.f);
    }
    for (int i = tid; i < PAIRS * 65; i += THREADS) {
        int pp = i / 65, k = i - pp * 65;
        a_sh[pp][k] = 2.f * amp[(pairBase + pp) * 65 + k];
    }
    __syncthreads();

    // ---- phase B: deposit s = 2u-1; taps via symmetric-pair DCT ----
    {
        float4 s4 = make_float4(2.f * v.x - 1.f, 2.f * v.y - 1.f,
                                2.f * v.z - 1.f, 2.f * v.w - 1.f);
        ((float4*)(Z[p]))[64 + q] = s4;                  // Z[256+4q .. +3]
    }
    if (tid < 132) {                                     // 33 workers per pair
        const int pp = tid & 3;
        const int jj = tid >> 2;                         // 0..32
        const float4* a4 = (const float4*)a_sh[pp];
        const float a64  = a_sh[pp][64];

        float e, o;
        int m;
        {   // quad 0: k = 0 (DC), 1, 2, 3
            float4 g = a4[0];
            e = 0.5f * g.x + ((jj & 1) ? -0.5f : 0.5f) * a64;
            m = jj;                                      // k=1
            o = g.y * __cosf((float)m * PI64);
            m = (m + jj) & 127;                          // k=2
            e = fmaf(g.z, __cosf((float)m * PI64), e);
            m = (m + jj) & 127;                          // k=3
            o = fmaf(g.w, __cosf((float)m * PI64), o);
        }
        #pragma unroll
        for (int i = 1; i < 16; i++) {                   // k = 4i .. 4i+3
            float4 g = a4[i];
            m = (m + jj) & 127; e = fmaf(g.x, __cosf((float)m * PI64), e);
            m = (m + jj) & 127; o = fmaf(g.y, __cosf((float)m * PI64), o);
            m = (m + jj) & 127; e = fmaf(g.z, __cosf((float)m * PI64), e);
            m = (m + jj) & 127; o = fmaf(g.w, __cosf((float)m * PI64), o);
        }
        float c1 = __cosf((float)jj * PI64);             // cos(pi*jj/64)
        float hj = (e + o) * (1.f + c1) * (1.f / 256.f); // tap jj
        uint64_t d0; PACK2(d0, hj, hj);
        hd64[pp][jj] = d0;
        if (jj >= 1) {                                   // partner tap 64-jj
            float hp = (e - o) * (1.f - c1) * (1.f / 256.f);
            uint64_t d1; PACK2(d1, hp, hp);
            hd64[pp][64 - jj] = d1;
        }
    }
    __syncthreads();

    // ---- phase C: convolution, 4 outputs/thread, packed FFMA2 ----
    {
        const float4* Z4 = (const float4*)(Z[p]);
        const uint32_t hbase = (uint32_t)__cvta_generic_to_shared(hd64[p]);
        const int base = 64 + q;                         // float4 idx of Z[256+t0]

        uint64_t o01 = 0ull, o23 = 0ull;
        float4 B = Z4[base];                             // causal window hi
        uint64_t Pb12; PACK2(Pb12, B.y, B.z);            // carried across iters

        if (q < 48) {
            #pragma unroll
            for (int dq = 0; dq < 16; dq++) {
                uint64_t H00, H11, H22, H33;
                LDSH2(H00, H11, hbase + 32 * dq);
                LDSH2(H22, H33, hbase + 32 * dq + 16);
                const float4 A = Z4[base - dq - 1];
                uint64_t Pb01, Pb23, Pa23, Pa12, Pa3b0;
                PACK2(Pb01, B.x, B.y);  PACK2(Pb23, B.z, B.w);   // aligned: elided
                PACK2(Pa23, A.z, A.w);
                PACK2(Pa12, A.y, A.z);  PACK2(Pa3b0, A.w, B.x);  // real MOVs
                FMA2(o01, H00, Pb01);  FMA2(o23, H00, Pb23);   // d=4dq
                FMA2(o01, H11, Pa3b0); FMA2(o23, H11, Pb12);   // d=4dq+1
                FMA2(o01, H22, Pa23);  FMA2(o23, H22, Pb01);   // d=4dq+2
                FMA2(o01, H33, Pa12);  FMA2(o23, H33, Pa3b0);  // d=4dq+3
                B = A;
                Pb12 = Pa12;                                   // next iter's Pb12
            }
        } else {
            float4 C = Z4[q];                            // tail window lo
            uint64_t Pc12; PACK2(Pc12, C.y, C.z);        // carried across iters
            #pragma unroll
            for (int dq = 0; dq < 16; dq++) {
                uint64_t H00, H11, H22, H33;
                LDSH2(H00, H11, hbase + 32 * dq);
                LDSH2(H22, H33, hbase + 32 * dq + 16);
                const float4 A = Z4[base - dq - 1];
                const float4 D = Z4[q + dq + 1];
                uint64_t Pb01, Pb23, Pa23, Pa12, Pa3b0;
                PACK2(Pb01, B.x, B.y);  PACK2(Pb23, B.z, B.w);
                PACK2(Pa23, A.z, A.w);  PACK2(Pa12, A.y, A.z);
                PACK2(Pa3b0, A.w, B.x);
                uint64_t Pc01, Pc23, Pc3d0, Pd01, Pd12;
                PACK2(Pc01, C.x, C.y);  PACK2(Pc23, C.z, C.w);
                PACK2(Pc3d0, C.w, D.x);
                PACK2(Pd01, D.x, D.y);  PACK2(Pd12, D.y, D.z);
                uint64_t S0, S1;
                ADD2(S0, Pb01, Pc01);  ADD2(S1, Pb23, Pc23);   // d=4dq
                FMA2(o01, H00, S0);    FMA2(o23, H00, S1);
                ADD2(S0, Pa3b0, Pc12); ADD2(S1, Pb12, Pc3d0);  // d=4dq+1
                FMA2(o01, H11, S0);    FMA2(o23, H11, S1);
                ADD2(S0, Pa23, Pc23);  ADD2(S1, Pb01, Pd01);   // d=4dq+2
                FMA2(o01, H22, S0);    FMA2(o23, H22, S1);
                ADD2(S0, Pa12, Pc3d0); ADD2(S1, Pa3b0, Pd12);  // d=4dq+3
                FMA2(o01, H33, S0);    FMA2(o23, H33, S1);
                B = A;  C = D;
                Pb12 = Pa12;  Pc12 = Pd12;
            }
        }

        uint32_t u0, u1, u2, u3;
        UNPACK2(u0, u1, o01);
        UNPACK2(u2, u3, o23);
        ((float4*)out)[(pairBase + p) * 64 + q] =
            make_float4(__uint_as_float(u0), __uint_as_float(u1),
                        __uint_as_float(u2), __uint_as_float(u3));
    }
}

extern "C" void kernel_launch(void* const* d_in, const int* in_sizes, int n_in,
                              void* d_out, int out_size)
{
    const float* amp   = (const float*)d_in[0];   // filter_bank [16,4096,65]
    const float* noise = (const float*)d_in[1];   // noise_u     [16,4096,256]
    float* out = (float*)d_out;                   // [16, 4096*256, 1]

    const int total_pairs = in_sizes[0] / 65;     // 65536
    const int blocks = total_pairs / PAIRS;       // 16384
    noisefilter_kernel<<<blocks, THREADS>>>(amp, noise, out);
}

// round 12
// speedup vs baseline: 1.6158x; 1.6158x over previous
#include <cuda_runtime.h>
#include <cuda_bf16.h>
#include <cstdint>

// NoiseFilter, exact closed form (validated R3-R11, rel_err ~3e-7):
//   taps: ir0[j] = (1/128)(amp0 + 2*sum_{k=1..63} amp_k cos(pi*k*j/64) + amp64*(-1)^j)
//         h[j]   = ir0[j] * 0.5*(1+cos(pi*j/64)),  j = 0..63
//   s[t] = 2*u[t]-1,  Z[192..255]=0, Z[256+t]=s[t]   (only [192,256) zeros are read)
//   out[tau] = sum_{d=0}^{63} h[d] * ( Z[256+tau-d] + Z[tau+d] )
// Wrap-tail (2nd term) only for output groups t0>=192 (q>=48): warps 6-7.
// Phase B: symmetric pairs — ir0(64-j)=E(j)-O(j), 33 workers/pair, coeffs read
// as LDS.128 quads. Taps stored duplicated (h,h) as uint64; conv loads them as
// C++ ulonglong2 (ld.shared.v2.u64, NON-volatile: schedulable, imm-foldable;
// the R11 asm-volatile variant serialized the loop and cost 1.6x).

#define PAIRS   4
#define THREADS 256
#define ZSTRIDE 520            // 512 + 8 pad (16B row alignment)
#define PI64    0.04908738521234052f   // pi/64

#define PACK2(dst, lo, hi) \
    asm("mov.b64 %0, {%1, %2};" : "=l"(dst) \
        : "r"(__float_as_uint(lo)), "r"(__float_as_uint(hi)))
#define FMA2(acc, a, b) \
    asm("fma.rn.f32x2 %0, %1, %2, %0;" : "+l"(acc) : "l"(a), "l"(b))
#define ADD2(dst, a, b) \
    asm("add.rn.f32x2 %0, %1, %2;" : "=l"(dst) : "l"(a), "l"(b))
#define UNPACK2(lo, hi, v) \
    asm("mov.b64 {%0, %1}, %2;" : "=r"(lo), "=r"(hi) : "l"(v))

__global__ __launch_bounds__(THREADS)
void noisefilter_kernel(const float* __restrict__ amp,    // [65536, 65]
                        const float* __restrict__ noise,  // [65536, 256]
                        float*       __restrict__ out)    // [65536, 256]
{
    __shared__ __align__(16) float    Z[PAIRS][ZSTRIDE];  // padded signal
    __shared__ __align__(16) uint64_t hd64[PAIRS][64];    // duplicated taps (h,h)
    __shared__ __align__(16) float    a_sh[PAIRS][68];    // 2*amp

    const int tid = threadIdx.x;

    // tid -> (p, q): q<48 (tail-free) fills warps 0..5; q>=48 warps 6..7.
    int p, q;
    if (tid < 192) { p = tid / 48;      q = tid % 48; }
    else           { int r = tid - 192; p = r >> 4;   q = 48 + (r & 15); }

    const long long pairBase = (long long)blockIdx.x * PAIRS;

    // ---- issue global noise load early ----
    const float4* n4 = (const float4*)noise;
    float4 v = n4[(pairBase + p) * 64 + q];

    // ---- phase A: zero only Z[192..256) per pair; load amp (doubled) ----
    if (tid < 64) {
        int pp  = tid >> 4;
        int idx = 48 + (tid & 15);           // float4 idx 48..63 = floats 192..255
        ((float4*)(Z[pp]))[idx] = make_float4(0.f, 0.f, 0.f, 0.f);
    }
    for (int i = tid; i < PAIRS * 65; i += THREADS) {
        int pp = i / 65, k = i - pp * 65;
        a_sh[pp][k] = 2.f * amp[(pairBase + pp) * 65 + k];
    }
    __syncthreads();

    // ---- phase B: deposit s = 2u-1; taps via symmetric-pair DCT ----
    {
        float4 s4 = make_float4(2.f * v.x - 1.f, 2.f * v.y - 1.f,
                                2.f * v.z - 1.f, 2.f * v.w - 1.f);
        ((float4*)(Z[p]))[64 + q] = s4;                  // Z[256+4q .. +3]
    }
    if (tid < 132) {                                     // 33 workers per pair
        const int pp = tid & 3;
        const int jj = tid >> 2;                         // 0..32
        const float4* a4 = (const float4*)a_sh[pp];
        const float a64  = a_sh[pp][64];

        float e, o;
        int m;
        {   // quad 0: k = 0 (DC), 1, 2, 3
            float4 g = a4[0];
            e = 0.5f * g.x + ((jj & 1) ? -0.5f : 0.5f) * a64;
            m = jj;                                      // k=1
            o = g.y * __cosf((float)m * PI64);
            m = (m + jj) & 127;                          // k=2
            e = fmaf(g.z, __cosf((float)m * PI64), e);
            m = (m + jj) & 127;                          // k=3
            o = fmaf(g.w, __cosf((float)m * PI64), o);
        }
        #pragma unroll
        for (int i = 1; i < 16; i++) {                   // k = 4i .. 4i+3
            float4 g = a4[i];
            m = (m + jj) & 127; e = fmaf(g.x, __cosf((float)m * PI64), e);
            m = (m + jj) & 127; o = fmaf(g.y, __cosf((float)m * PI64), o);
            m = (m + jj) & 127; e = fmaf(g.z, __cosf((float)m * PI64), e);
            m = (m + jj) & 127; o = fmaf(g.w, __cosf((float)m * PI64), o);
        }
        float c1 = __cosf((float)jj * PI64);             // cos(pi*jj/64)
        float hj = (e + o) * (1.f + c1) * (1.f / 256.f); // tap jj
        uint64_t d0; PACK2(d0, hj, hj);
        hd64[pp][jj] = d0;
        if (jj >= 1) {                                   // partner tap 64-jj
            float hp = (e - o) * (1.f - c1) * (1.f / 256.f);
            uint64_t d1; PACK2(d1, hp, hp);
            hd64[pp][64 - jj] = d1;
        }
    }
    __syncthreads();

    // ---- phase C: convolution, 4 outputs/thread, packed FFMA2 ----
    {
        const float4*     Z4 = (const float4*)(Z[p]);
        const ulonglong2* H2 = (const ulonglong2*)(hd64[p]);  // (h2d,h2d),(h2d+1,h2d+1)
        const int base = 64 + q;                         // float4 idx of Z[256+t0]

        uint64_t o01 = 0ull, o23 = 0ull;
        float4 B = Z4[base];                             // causal window hi
        uint64_t Pb12; PACK2(Pb12, B.y, B.z);            // carried across iters

        if (q < 48) {
            #pragma unroll
            for (int dq = 0; dq < 16; dq++) {
                const ulonglong2 Hp = H2[2 * dq];        // (h0,h0),(h1,h1)
                const ulonglong2 Hq = H2[2 * dq + 1];    // (h2,h2),(h3,h3)
                const float4 A = Z4[base - dq - 1];
                uint64_t Pb01, Pb23, Pa23, Pa12, Pa3b0;
                PACK2(Pb01, B.x, B.y);  PACK2(Pb23, B.z, B.w);   // aligned: elided
                PACK2(Pa23, A.z, A.w);
                PACK2(Pa12, A.y, A.z);  PACK2(Pa3b0, A.w, B.x);  // real MOVs
                FMA2(o01, Hp.x, Pb01);  FMA2(o23, Hp.x, Pb23);   // d=4dq
                FMA2(o01, Hp.y, Pa3b0); FMA2(o23, Hp.y, Pb12);   // d=4dq+1
                FMA2(o01, Hq.x, Pa23);  FMA2(o23, Hq.x, Pb01);   // d=4dq+2
                FMA2(o01, Hq.y, Pa12);  FMA2(o23, Hq.y, Pa3b0);  // d=4dq+3
                B = A;
                Pb12 = Pa12;                                     // next iter's Pb12
            }
        } else {
            float4 C = Z4[q];                            // tail window lo
            uint64_t Pc12; PACK2(Pc12, C.y, C.z);        // carried across iters
            #pragma unroll
            for (int dq = 0; dq < 16; dq++) {
                const ulonglong2 Hp = H2[2 * dq];
                const ulonglong2 Hq = H2[2 * dq + 1];
                const float4 A = Z4[base - dq - 1];
                const float4 D = Z4[q + dq + 1];
                uint64_t Pb01, Pb23, Pa23, Pa12, Pa3b0;
                PACK2(Pb01, B.x, B.y);  PACK2(Pb23, B.z, B.w);
                PACK2(Pa23, A.z, A.w);  PACK2(Pa12, A.y, A.z);
                PACK2(Pa3b0, A.w, B.x);
                uint64_t Pc01, Pc23, Pc3d0, Pd01, Pd12;
                PACK2(Pc01, C.x, C.y);  PACK2(Pc23, C.z, C.w);
                PACK2(Pc3d0, C.w, D.x);
                PACK2(Pd01, D.x, D.y);  PACK2(Pd12, D.y, D.z);
                uint64_t S0, S1;
                ADD2(S0, Pb01, Pc01);  ADD2(S1, Pb23, Pc23);     // d=4dq
                FMA2(o01, Hp.x, S0);   FMA2(o23, Hp.x, S1);
                ADD2(S0, Pa3b0, Pc12); ADD2(S1, Pb12, Pc3d0);    // d=4dq+1
                FMA2(o01, Hp.y, S0);   FMA2(o23, Hp.y, S1);
                ADD2(S0, Pa23, Pc23);  ADD2(S1, Pb01, Pd01);     // d=4dq+2
                FMA2(o01, Hq.x, S0);   FMA2(o23, Hq.x, S1);
                ADD2(S0, Pa12, Pc3d0); ADD2(S1, Pa3b0, Pd12);    // d=4dq+3
                FMA2(o01, Hq.y, S0);   FMA2(o23, Hq.y, S1);
                B = A;  C = D;
                Pb12 = Pa12;  Pc12 = Pd12;
            }
        }

        uint32_t u0, u1, u2, u3;
        UNPACK2(u0, u1, o01);
        UNPACK2(u2, u3, o23);
        ((float4*)out)[(pairBase + p) * 64 + q] =
            make_float4(__uint_as_float(u0), __uint_as_float(u1),
                        __uint_as_float(u2), __uint_as_float(u3));
    }
}

extern "C" void kernel_launch(void* const* d_in, const int* in_sizes, int n_in,
                              void* d_out, int out_size)
{
    const float* amp   = (const float*)d_in[0];   // filter_bank [16,4096,65]
    const float* noise = (const float*)d_in[1];   // noise_u     [16,4096,256]
    float* out = (float*)d_out;                   // [16, 4096*256, 1]

    const int total_pairs = in_sizes[0] / 65;     // 65536
    const int blocks = total_pairs / PAIRS;       // 16384
    noisefilter_kernel<<<blocks, THREADS>>>(amp, noise, out);
}